// round 4
// baseline (speedup 1.0000x reference)
#include <cuda_runtime.h>

#define NSTEP  25
#define NIN    9
#define NHID   100
#define NPAD   104          // padded so each half-thread gets 13 groups of 4

__global__ __launch_bounds__(128) void snn_kernel(
    const float* __restrict__ x,
    const float* __restrict__ W1,
    const float* __restrict__ b1,
    const float* __restrict__ W2,
    const float* __restrict__ b2,
    float* __restrict__ out,
    int batch)
{
    // W1 padded to 12 floats/row: [w0..w8, b1, 0, 0] -> 3x LDS.128 per neuron
    __shared__ float4 sW1[NPAD * 3];
    __shared__ float2 sW2[NPAD];   // (W2[0][h], W2[1][h])
    __shared__ float  sb2[2];

    {
        float* sW1f = (float*)sW1;
        for (int h = threadIdx.x; h < NPAD; h += blockDim.x) {
            if (h < NHID) {
#pragma unroll
                for (int i = 0; i < NIN; i++) sW1f[h * 12 + i] = W1[h * NIN + i];
                sW1f[h * 12 + 9] = b1[h];
                sW2[h] = make_float2(W2[h], W2[NHID + h]);
            } else {
#pragma unroll
                for (int i = 0; i < 10; i++) sW1f[h * 12 + i] = 0.0f;
                sW2[h] = make_float2(0.0f, 0.0f);
            }
            sW1f[h * 12 + 10] = 0.0f;
            sW1f[h * 12 + 11] = 0.0f;
        }
        if (threadIdx.x < 2) sb2[threadIdx.x] = b2[threadIdx.x];
    }
    __syncthreads();

    int gt   = blockIdx.x * blockDim.x + threadIdx.x;
    int b    = gt >> 1;
    int half = gt & 1;          // lane pair splits the hidden layer 52/52
    if (b >= batch) return;

    float xv[NIN];
#pragma unroll
    for (int i = 0; i < NIN; i++) xv[i] = __ldg(&x[(size_t)b * NIN + i]);

    float acc0[NSTEP], acc1[NSTEP];
#pragma unroll
    for (int t = 0; t < NSTEP; t++) { acc0[t] = 0.0f; acc1[t] = 0.0f; }

    const int hbase = half * (NPAD / 2);   // 0 or 52

    // 13 groups of 4 neurons; 4 independent recurrence chains per group.
    for (int g = 0; g < NPAD / 2 / 4; g++) {
        const int h = hbase + g * 4;
        float c[4];
#pragma unroll
        for (int j = 0; j < 4; j++) {
            float4 a0 = sW1[(h + j) * 3 + 0];
            float4 a1 = sW1[(h + j) * 3 + 1];
            float4 a2 = sW1[(h + j) * 3 + 2];
            float cc = a2.y;                       // bias in padded slot 9
            cc = fmaf(xv[0], a0.x, cc); cc = fmaf(xv[1], a0.y, cc);
            cc = fmaf(xv[2], a0.z, cc); cc = fmaf(xv[3], a0.w, cc);
            cc = fmaf(xv[4], a1.x, cc); cc = fmaf(xv[5], a1.y, cc);
            cc = fmaf(xv[6], a1.z, cc); cc = fmaf(xv[7], a1.w, cc);
            cc = fmaf(xv[8], a2.x, cc);
            c[j] = cc;
        }
        float2 w0 = sW2[h], w1 = sW2[h + 1], w2 = sW2[h + 2], w3 = sW2[h + 3];

        float m0 = 0.f, m1 = 0.f, m2 = 0.f, m3 = 0.f;   // membranes
        float r0 = 0.f, r1 = 0.f, r2 = 0.f, r3 = 0.f;   // spikes (float 0/1)

        // Per neuron-step (5 instr): FFMA-imm, FADD, FSET, FFMA, FFMA
#pragma unroll
        for (int t = 0; t < NSTEP; t++) {
            m0 = fmaf(0.95f, m0, c[0]) - r0;
            m1 = fmaf(0.95f, m1, c[1]) - r1;
            m2 = fmaf(0.95f, m2, c[2]) - r2;
            m3 = fmaf(0.95f, m3, c[3]) - r3;
            asm("set.gt.f32.f32 %0, %1, 0f3F800000;" : "=f"(r0) : "f"(m0));
            asm("set.gt.f32.f32 %0, %1, 0f3F800000;" : "=f"(r1) : "f"(m1));
            asm("set.gt.f32.f32 %0, %1, 0f3F800000;" : "=f"(r2) : "f"(m2));
            asm("set.gt.f32.f32 %0, %1, 0f3F800000;" : "=f"(r3) : "f"(m3));
            acc0[t] = fmaf(r0, w0.x, acc0[t]);  acc1[t] = fmaf(r0, w0.y, acc1[t]);
            acc0[t] = fmaf(r1, w1.x, acc0[t]);  acc1[t] = fmaf(r1, w1.y, acc1[t]);
            acc0[t] = fmaf(r2, w2.x, acc0[t]);  acc1[t] = fmaf(r2, w2.y, acc1[t]);
            acc0[t] = fmaf(r3, w3.x, acc0[t]);  acc1[t] = fmaf(r3, w3.y, acc1[t]);
        }
    }

    // Combine the two half-sums across the lane pair (both lanes get total)
#pragma unroll
    for (int t = 0; t < NSTEP; t++) {
        acc0[t] += __shfl_xor_sync(0xffffffffu, acc0[t], 1);
        acc1[t] += __shfl_xor_sync(0xffffffffu, acc1[t], 1);
    }

    // Layer-2 LIF recurrence; lane pair splits the 25 stores (t<13 / t>=13)
    const float bb0 = sb2[0], bb1 = sb2[1];
    float m20 = 0.0f, m21 = 0.0f;
    float2* outv = (float2*)out;
#pragma unroll
    for (int t = 0; t < NSTEP; t++) {
        float rr0, rr1;                               // reset from PREVIOUS mem2
        asm("set.gt.f32.f32 %0, %1, 0f3F800000;" : "=f"(rr0) : "f"(m20));
        asm("set.gt.f32.f32 %0, %1, 0f3F800000;" : "=f"(rr1) : "f"(m21));
        m20 = fmaf(0.95f, m20, acc0[t] + bb0) - rr0;
        m21 = fmaf(0.95f, m21, acc1[t] + bb1) - rr1;
        bool mine = (half == 0) ? (t < 13) : (t >= 13);
        if (mine) outv[(size_t)t * batch + b] = make_float2(m20, m21);
    }
}

extern "C" void kernel_launch(void* const* d_in, const int* in_sizes, int n_in,
                              void* d_out, int out_size)
{
    const float* x  = (const float*)d_in[0];
    const float* W1 = (const float*)d_in[1];
    const float* b1 = (const float*)d_in[2];
    const float* W2 = (const float*)d_in[3];
    const float* b2 = (const float*)d_in[4];
    float* out = (float*)d_out;

    int batch = in_sizes[0] / NIN;
    const int threads = 128;               // 64 batch elems / block
    long long total = (long long)batch * 2; // 2 threads per batch element
    int blocks = (int)((total + threads - 1) / threads);
    snn_kernel<<<blocks, threads>>>(x, W1, b1, W2, b2, out, batch);
}